// round 15
// baseline (speedup 1.0000x reference)
#include <cuda_runtime.h>

#define BB 8
#define NN 2048
#define BN (BB * NN)
#define CC 128
#define HH 4
#define DD 32
#define SS 3
#define KNB 16
#define KT 48
#define MT 32          // GEMM m-tile (fused k-paired version)
#define APP 8          // points per attn block (1 warp each)
#define NJOB 54        // 48 nbr + 3 own + 3 bk
#define CAP 256        // knn candidate capacity per warp

#define FULLMASK 0xffffffffu
typedef unsigned long long ull;

__device__ int   g_knn[BN * KT];
__device__ float g_Q[BN * CC];
__device__ float g_V[BN * CC];
__device__ float g_KF[(SS * BN + SS) * CC];   // + SS rows of bk at the tail
__device__ ull   g_Wp[5 * 64 * CC];           // k-paired weights (W[2k2][c], W[2k2+1][c])

// ---- f32x2 packed helpers (full fp32 precision, 2 ops / instr) ------------
__device__ __forceinline__ ull pk2(float lo, float hi) {
    ull r; asm("mov.b64 %0, {%1,%2};" : "=l"(r) : "f"(lo), "f"(hi)); return r;
}
__device__ __forceinline__ void fma2(ull& d, ull a, ull b) {
    asm("fma.rn.f32x2 %0, %1, %2, %0;" : "+l"(d) : "l"(a), "l"(b));
}
__device__ __forceinline__ ull mul2(ull a, ull b) {
    ull r; asm("mul.rn.f32x2 %0, %1, %2;" : "=l"(r) : "l"(a), "l"(b)); return r;
}
__device__ __forceinline__ ull add2(ull a, ull b) {
    ull r; asm("add.rn.f32x2 %0, %1, %2;" : "=l"(r) : "l"(a), "l"(b)); return r;
}
__device__ __forceinline__ float2 upk2(ull v) {
    float2 f; asm("mov.b64 {%0,%1}, %2;" : "=f"(f.x), "=f"(f.y) : "l"(v)); return f;
}
__device__ __forceinline__ unsigned mapk(float f) {
    unsigned u = __float_as_uint(f);
    return u ^ (unsigned)(((int)u >> 31) | 0x80000000);   // monotone total order
}

// ---------------------------------------------------------------------------
// Kernel 0: prep — k-paired weights + bk tail rows of g_KF.
// ---------------------------------------------------------------------------
__global__ __launch_bounds__(256) void prep_kernel(
    const float* __restrict__ Wq, const float* __restrict__ Wv,
    const float* __restrict__ Wk, const float* __restrict__ bk) {
    const int id = blockIdx.x * 256 + threadIdx.x;
    if (id < 5 * 64 * CC) {
        int y = id >> 13, r = id & 8191, k2 = r >> 7, c = r & 127;
        const float* Ws = (y == 0) ? Wq : (y == 1) ? Wv : Wk + (y - 2) * CC * CC;
        g_Wp[id] = pk2(Ws[(2 * k2) * CC + c], Ws[(2 * k2 + 1) * CC + c]);
    } else if (id - 5 * 64 * CC < SS * CC) {
        int r = id - 5 * 64 * CC;
        g_KF[(size_t)(SS * BN + r / CC) * CC + (r % CC)] = bk[r];
    }
}

// ---------------------------------------------------------------------------
// Shared-memory layouts for the fused kernel (union via dynamic smem)
// ---------------------------------------------------------------------------
struct KnnS {
    ulonglong2 cA[NN / 2];  // pair i: ((x2i,x2i+1),(y2i,y2i+1))   16 KB
    ulonglong2 cB[NN / 2];  // pair i: ((z2i,z2i+1),(sq…))         16 KB
    ull cand[8][CAP];       // compacted candidates                16 KB
    ull buf[8][64];         // sort buffer                          4 KB
};
struct GemmS {
    float XsT[CC][34];      // A tile transposed [k][m]            17.4 KB
    ull   As[64][34];       // A k-pairs [k2][m]                   17.4 KB
};

// ---------------------------------------------------------------------------
// kNN body: packed f32x2 distances, two-pass (min-track, recompute+compact).
// One warp per query, 8 queries/block. Exact (dist, idx) top-48.
// ---------------------------------------------------------------------------
__device__ __forceinline__ void knn_body(char* smraw, const float* __restrict__ coord,
                                         int bx) {
    KnnS* K = (KnnS*)smraw;
    const int t = threadIdx.x;
    const int lane = t & 31, w = t >> 5;
    const int b = bx >> 8;                 // 256 blocks per batch
    const int n0 = (bx & 255) * 8;
    const float* cb = coord + (size_t)b * NN * 3;

    // load coords as candidate-pairs with |p|^2 (same fmaf association as ref)
    for (int i = t; i < NN / 2; i += 256) {
        float2 f0 = *(const float2*)&cb[6 * i];
        float2 f1 = *(const float2*)&cb[6 * i + 2];
        float2 f2 = *(const float2*)&cb[6 * i + 4];
        float x0 = f0.x, y0 = f0.y, z0 = f1.x;
        float x1 = f1.y, y1 = f2.x, z1 = f2.y;
        float sq0 = fmaf(x0, x0, fmaf(y0, y0, z0 * z0));
        float sq1 = fmaf(x1, x1, fmaf(y1, y1, z1 * z1));
        K->cA[i] = make_ulonglong2(pk2(x0, x1), pk2(y0, y1));
        K->cB[i] = make_ulonglong2(pk2(z0, z1), pk2(sq0, sq1));
    }
    __syncthreads();

    const int n = n0 + w;
    float ox, oy, oz, osq;
    {
        ulonglong2 A = K->cA[n >> 1], B = K->cB[n >> 1];
        float2 xx = upk2(A.x), yy = upk2(A.y), zz = upk2(B.x), ss = upk2(B.y);
        int h = n & 1;
        ox = h ? xx.y : xx.x; oy = h ? yy.y : yy.x;
        oz = h ? zz.y : zz.x; osq = h ? ss.y : ss.x;
    }
    const ull ox2 = pk2(ox, ox), oy2 = pk2(oy, oy), oz2 = pk2(oz, oz);
    const ull osq2 = pk2(osq, osq), neg2 = pk2(-2.0f, -2.0f);

    // ---- pass 1: per-lane (min1, min2) over 64 candidates (32 pairs) ----
    float m1f = 3.4e38f, m2f = 3.4e38f;
    #pragma unroll
    for (int s = 0; s < 32; s++) {
        int pi = lane + (s << 5);
        ulonglong2 A = K->cA[pi], B = K->cB[pi];
        ull m = mul2(oz2, B.x);          // oz*z
        fma2(m, oy2, A.y);               // + oy*y
        fma2(m, ox2, A.x);               // + ox*x  (matches ref association)
        ull dsum = add2(osq2, B.y);      // osq + csq
        fma2(dsum, neg2, m);             // + (-2)*dot
        float2 df = upk2(dsum);
        float hx = fmaxf(m1f, df.x);
        m2f = fminf(m2f, hx); m1f = fminf(m1f, df.x);
        float hy = fmaxf(m1f, df.y);
        m2f = fminf(m2f, hy); m1f = fminf(m1f, df.y);
    }

    unsigned lo = __reduce_min_sync(FULLMASK, mapk(m1f));
    float hiF = m2f;
    #pragma unroll
    for (int off = 16; off; off >>= 1)
        hiF = fmaxf(hiF, __shfl_xor_sync(FULLMASK, hiF, off));
    unsigned hi = mapk(hiF);             // >= 64 keys <= hiF guaranteed

    // ---- pass 2: recompute + ballot-compact (float compare, mapped store) ----
    int base = 0;
    #pragma unroll
    for (int s = 0; s < 32; s++) {
        int pi = lane + (s << 5);
        ulonglong2 A = K->cA[pi], B = K->cB[pi];
        ull m = mul2(oz2, B.x);
        fma2(m, oy2, A.y);
        fma2(m, ox2, A.x);
        ull dsum = add2(osq2, B.y);
        fma2(dsum, neg2, m);
        float2 df = upk2(dsum);
        bool q0 = (df.x <= hiF);
        unsigned mm = __ballot_sync(FULLMASK, q0);
        if (q0) {
            int pos = base + __popc(mm & ((1u << lane) - 1u));
            if (pos < CAP)
                K->cand[w][pos] = ((ull)mapk(df.x) << 32) | (unsigned)(2 * pi);
        }
        base += __popc(mm);
        bool q1 = (df.y <= hiF);
        mm = __ballot_sync(FULLMASK, q1);
        if (q1) {
            int pos = base + __popc(mm & ((1u << lane) - 1u));
            if (pos < CAP)
                K->cand[w][pos] = ((ull)mapk(df.y) << 32) | (unsigned)(2 * pi + 1);
        }
        base += __popc(mm);
    }
    __syncwarp();

    unsigned T;
    K->buf[w][lane] = ~0ull;
    K->buf[w][lane + 32] = ~0ull;
    __syncwarp();

    if (base <= CAP) {
        // ---- binary search over <= 8 candidates per lane ----
        unsigned ck[8];
        #pragma unroll
        for (int sl = 0; sl < 8; sl++) {
            int p = lane + (sl << 5);
            ck[sl] = (p < base) ? (unsigned)(K->cand[w][p] >> 32) : 0xffffffffu;
        }
        for (;;) {
            if (lo >= hi) { T = lo; break; }
            unsigned mid = lo + ((hi - lo) >> 1);
            unsigned c = 0;
            #pragma unroll
            for (int sl = 0; sl < 8; sl++) c += (ck[sl] <= mid) ? 1u : 0u;
            c = __reduce_add_sync(FULLMASK, c);
            if (c == KT) { T = mid; break; }
            if (c > KT) hi = mid; else lo = mid + 1;
        }
        int bs = 0;
        #pragma unroll
        for (int sl = 0; sl < 8; sl++) {
            int p = lane + (sl << 5);
            bool q = (ck[sl] <= T);
            unsigned mm = __ballot_sync(FULLMASK, q);
            if (q) {
                int pos = bs + __popc(mm & ((1u << lane) - 1u));
                if (pos < 64) K->buf[w][pos] = K->cand[w][p];
            }
            bs += __popc(mm);
        }
    } else {
        // ---- ultra-rare fallback: recompute-count binary search ----
        for (;;) {
            if (lo >= hi) { T = lo; break; }
            unsigned mid = lo + ((hi - lo) >> 1);
            unsigned c = 0;
            #pragma unroll 8
            for (int s = 0; s < 32; s++) {
                int pi = lane + (s << 5);
                ulonglong2 A = K->cA[pi], B = K->cB[pi];
                ull m = mul2(oz2, B.x);
                fma2(m, oy2, A.y);
                fma2(m, ox2, A.x);
                ull dsum = add2(osq2, B.y);
                fma2(dsum, neg2, m);
                float2 df = upk2(dsum);
                c += (mapk(df.x) <= mid) ? 1u : 0u;
                c += (mapk(df.y) <= mid) ? 1u : 0u;
            }
            c = __reduce_add_sync(FULLMASK, c);
            if (c == KT) { T = mid; break; }
            if (c > KT) hi = mid; else lo = mid + 1;
        }
        int bs = 0;
        #pragma unroll 8
        for (int s = 0; s < 32; s++) {
            int pi = lane + (s << 5);
            ulonglong2 A = K->cA[pi], B = K->cB[pi];
            ull m = mul2(oz2, B.x);
            fma2(m, oy2, A.y);
            fma2(m, ox2, A.x);
            ull dsum = add2(osq2, B.y);
            fma2(dsum, neg2, m);
            float2 df = upk2(dsum);
            #pragma unroll
            for (int hh = 0; hh < 2; hh++) {
                unsigned u = mapk(hh ? df.y : df.x);
                bool q = (u <= T);
                unsigned mm = __ballot_sync(FULLMASK, q);
                if (q) {
                    int pos = bs + __popc(mm & ((1u << lane) - 1u));
                    if (pos < 64)
                        K->buf[w][pos] = ((ull)u << 32) | (unsigned)(2 * pi + hh);
                }
                bs += __popc(mm);
            }
        }
    }
    __syncwarp();

    // ---- bitonic sort of 64 u64 keys, 2 per lane -> exact (dist, idx) order
    ull v0 = K->buf[w][lane];
    ull v1 = K->buf[w][lane + 32];
    #pragma unroll
    for (int k2 = 2; k2 <= 64; k2 <<= 1) {
        #pragma unroll
        for (int j2 = k2 >> 1; j2 > 0; j2 >>= 1) {
            if (j2 == 32) {
                ull a = v0 < v1 ? v0 : v1;
                ull bm = v0 < v1 ? v1 : v0;
                v0 = a; v1 = bm;
            } else {
                bool low = ((lane & j2) == 0);
                bool up0 = ((lane & k2) == 0);
                bool up1 = (((lane + 32) & k2) == 0);
                ull o0 = __shfl_xor_sync(FULLMASK, v0, j2);
                ull o1 = __shfl_xor_sync(FULLMASK, v1, j2);
                bool t0 = (low == up0);
                bool t1 = (low == up1);
                v0 = t0 ? (v0 < o0 ? v0 : o0) : (v0 > o0 ? v0 : o0);
                v1 = t1 ? (v1 < o1 ? v1 : o1) : (v1 > o1 ? v1 : o1);
            }
        }
    }

    int* outp = g_knn + ((size_t)b * NN + n) * KT;
    outp[lane] = (int)(v0 & 0xffffffffu);
    if (lane < KT - 32) outp[32 + lane] = (int)(v1 & 0xffffffffu);
}

// ---------------------------------------------------------------------------
// GEMM body: k-paired f32x2, MT=32 rows x 128 cols, 256 threads (unchanged).
// ---------------------------------------------------------------------------
__device__ __forceinline__ void gemm_body(char* smraw,
                                          const float* __restrict__ A,
                                          const ull* __restrict__ wbase,
                                          const float* __restrict__ bias,
                                          float* __restrict__ O, int m0) {
    GemmS* G = (GemmS*)smraw;
    const int t = threadIdx.x;
    const int tx = t & 31, ty = t >> 5;    // ty 0..7 -> rows ty*4..ty*4+3

    #pragma unroll
    for (int s = t; s < MT * 32; s += 256) {
        int m = s >> 5, j = s & 31;
        float4 v = *(const float4*)&A[(size_t)(m0 + m) * CC + 4 * j];
        G->XsT[4 * j + 0][m] = v.x;
        G->XsT[4 * j + 1][m] = v.y;
        G->XsT[4 * j + 2][m] = v.z;
        G->XsT[4 * j + 3][m] = v.w;
    }
    __syncthreads();

    #pragma unroll
    for (int i = t; i < 64 * MT; i += 256) {
        int k2 = i >> 5, m = i & 31;
        *(float2*)&G->As[k2][m] = make_float2(G->XsT[2 * k2][m], G->XsT[2 * k2 + 1][m]);
    }
    __syncthreads();

    ull acc[4][4];
    #pragma unroll
    for (int mi = 0; mi < 4; mi++)
        #pragma unroll
        for (int ci = 0; ci < 4; ci++) acc[mi][ci] = 0;

    #pragma unroll 8
    for (int k2 = 0; k2 < 64; k2++) {
        const ulonglong2* wrow = (const ulonglong2*)(wbase + k2 * CC);
        ulonglong2 q0 = __ldg(wrow + tx);        // cols 2tx, 2tx+1
        ulonglong2 q1 = __ldg(wrow + 32 + tx);   // cols 64+2tx, 64+2tx+1
        ulonglong2 a01 = *(const ulonglong2*)&G->As[k2][ty * 4];
        ulonglong2 a23 = *(const ulonglong2*)&G->As[k2][ty * 4 + 2];
        fma2(acc[0][0], a01.x, q0.x); fma2(acc[0][1], a01.x, q0.y);
        fma2(acc[0][2], a01.x, q1.x); fma2(acc[0][3], a01.x, q1.y);
        fma2(acc[1][0], a01.y, q0.x); fma2(acc[1][1], a01.y, q0.y);
        fma2(acc[1][2], a01.y, q1.x); fma2(acc[1][3], a01.y, q1.y);
        fma2(acc[2][0], a23.x, q0.x); fma2(acc[2][1], a23.x, q0.y);
        fma2(acc[2][2], a23.x, q1.x); fma2(acc[2][3], a23.x, q1.y);
        fma2(acc[3][0], a23.y, q0.x); fma2(acc[3][1], a23.y, q0.y);
        fma2(acc[3][2], a23.y, q1.x); fma2(acc[3][3], a23.y, q1.y);
    }

    float2 b0 = *(const float2*)&bias[2 * tx];
    float2 b1 = *(const float2*)&bias[64 + 2 * tx];
    #pragma unroll
    for (int mi = 0; mi < 4; mi++) {
        int m = m0 + ty * 4 + mi;
        float2 f00 = upk2(acc[mi][0]), f01 = upk2(acc[mi][1]);
        float2 f10 = upk2(acc[mi][2]), f11 = upk2(acc[mi][3]);
        float2 r0 = make_float2(f00.x + f00.y + b0.x, f01.x + f01.y + b0.y);
        float2 r1 = make_float2(f10.x + f10.y + b1.x, f11.x + f11.y + b1.y);
        *(float2*)&O[(size_t)m * CC + 2 * tx] = r0;
        *(float2*)&O[(size_t)m * CC + 64 + 2 * tx] = r1;
    }
}

// ---------------------------------------------------------------------------
// Fused kNN + GEMM kernel: 256 groups x (8 knn + 10 gemm) blocks.
// ---------------------------------------------------------------------------
__global__ __launch_bounds__(256, 3) void fused_kg_kernel(
    const float* __restrict__ coord, const float* __restrict__ pcd,
    const float* __restrict__ bq, const float* __restrict__ bk,
    const float* __restrict__ bv) {
    extern __shared__ char smraw[];
    const int grp = blockIdx.x / 18;      // 0..255
    const int r   = blockIdx.x % 18;
    if (r < 8) {
        knn_body(smraw, coord, grp * 8 + r);           // 2048 knn blocks
    } else {
        int gid = grp * 10 + (r - 8);                  // 0..2559
        int y = gid >> 9, mblk = gid & 511;            // 5 x 512 m-tiles
        const ull* wbase = g_Wp + (size_t)y * 64 * CC;
        const float* bias;
        float* O;
        if (y == 0)      { bias = bq; O = g_Q; }
        else if (y == 1) { bias = bv; O = g_V; }
        else             { bias = bk + (y - 2) * CC; O = g_KF + (size_t)(y - 2) * BN * CC; }
        gemm_body(smraw, pcd, wbase, bias, O, mblk * MT);
    }
}

// ---------------------------------------------------------------------------
// Kernel 2: attention via Kf gathers — software-pipelined chunk loop.
// ---------------------------------------------------------------------------
__global__ __launch_bounds__(256, 4) void attn_kernel(float* __restrict__ out)
{
    __shared__ int   s_kn[APP][KT];
    __shared__ float s_raw[APP][HH][56];
    __shared__ float s_attn[APP][HH];

    const int t = threadIdx.x;
    const int lane = t & 31, w = t >> 5;
    const int g = lane & 7, kq = lane >> 3;
    const int b = blockIdx.x / (NN / APP);
    const int n0 = (blockIdx.x % (NN / APP)) * APP;
    const int gbase = b * NN;

    for (int idx = t; idx < APP * KT; idx += 256) {
        int p = idx / KT, j = idx % KT;
        s_kn[p][j] = g_knn[(size_t)(gbase + n0 + p) * KT + j];
    }
    __syncthreads();

    const int n = n0 + w;

    ulonglong2 qm[4];
    {
        const float* qrow = g_Q + (size_t)(gbase + n) * CC;
        #pragma unroll
        for (int m = 0; m < 4; m++)
            qm[m] = *(const ulonglong2*)&qrow[4 * g + 32 * m];
    }

    auto job_ext = [&](int jid) -> int {
        int i = (jid >= 36) ? 2 : (jid >= 18 ? 1 : 0);
        int r = jid - 18 * i;
        if (r < 16)  return i * BN + gbase + s_kn[w][i * KNB + r];
        if (r == 16) return i * BN + gbase + n;
        return SS * BN + i;
    };
    int je0 = job_ext(lane);
    int je1 = (lane < NJOB - 32) ? job_ext(32 + lane) : je0;

    // ---- prologue: load chunk 0 ----
    ulonglong2 c0, c1, c2, c3;
    {
        int jext = __shfl_sync(FULLMASK, je0, kq);
        const float* kf = g_KF + (size_t)jext * CC;
        c0 = *(const ulonglong2*)&kf[4 * g];
        c1 = *(const ulonglong2*)&kf[4 * g + 32];
        c2 = *(const ulonglong2*)&kf[4 * g + 64];
        c3 = *(const ulonglong2*)&kf[4 * g + 96];
    }

    #pragma unroll
    for (int ch = 0; ch < 14; ch++) {
        // ---- prefetch chunk ch+1 ----
        ulonglong2 p0, p1, p2, p3;
        if (ch < 13) {
            int chn = ch + 1;
            int src = (chn < 8) ? (4 * chn + kq) : (4 * (chn - 8) + kq);
            int jn = __shfl_sync(FULLMASK, (chn < 8) ? je0 : je1, src);
            const float* kfn = g_KF + (size_t)jn * CC;
            p0 = *(const ulonglong2*)&kfn[4 * g];
            p1 = *(const ulonglong2*)&kfn[4 * g + 32];
            p2 = *(const ulonglong2*)&kfn[4 * g + 64];
            p3 = *(const ulonglong2*)&kfn[4 * g + 96];
        }

        // ---- reduce current chunk ----
        ull a0 = 0, a1 = 0, a2 = 0, a3 = 0;
        fma2(a0, c0.x, qm[0].x); fma2(a0, c0.y, qm[0].y);
        fma2(a1, c1.x, qm[1].x); fma2(a1, c1.y, qm[1].y);
        fma2(a2, c2.x, qm[2].x); fma2(a2, c2.y, qm[2].y);
        fma2(a3, c3.x, qm[3].x); fma2(a3, c3.y, qm[3].y);
        float2 f0 = upk2(a0), f1 = upk2(a1), f2 = upk2(a2), f3 = upk2(a3);
        float s0 = f0.x + f0.y, s1 = f1.x + f1.y;
        float s2 = f2.x + f2.y, s3 = f3.x + f3.y;
        #pragma unroll
        for (int off = 1; off <= 4; off <<= 1) {
            s0 += __shfl_xor_sync(FULLMASK, s0, off);
            s1 += __shfl_xor_sync(FULLMASK, s1, off);
            s2 += __shfl_xor_sync(FULLMASK, s2, off);
            s3 += __shfl_xor_sync(FULLMASK, s3, off);
        }
        int jid = (ch < 8) ? (4 * ch + kq) : (32 + 4 * (ch - 8) + kq);
        float val = (g == 0) ? s0 : (g == 1) ? s1 : (g == 2) ? s2 : s3;
        if (g < 4 && jid < NJOB) s_raw[w][g][jid] = val;

        if (ch < 13) { c0 = p0; c1 = p1; c2 = p2; c3 = p3; }
    }
    __syncthreads();

    if (t < APP * HH) {
        const int p = t >> 2, h = t & 3;
        const float inv = 0.17677669529663687f;   // 1/sqrt(32)
        float accA = 0.0f;
        #pragma unroll
        for (int i = 0; i < SS; i++) {
            const float* raw = &s_raw[p][h][i * 18];
            float corr = raw[17] - raw[16];        // q.bk - q.Kf'[n]
            float l[KNB];
            float mx = -1e30f;
            #pragma unroll
            for (int k = 0; k < KNB; k++) {
                l[k] = inv * (raw[k] + corr);
                mx = fmaxf(mx, l[k]);
            }
            float se = 0.0f, sl = 0.0f;
            #pragma unroll
            for (int k = 0; k < KNB; k++) {
                float e = __expf(l[k] - mx);
                se += e;
                sl = fmaf(e, l[k], sl);
            }
            accA += sl / se;
        }
        s_attn[p][h] = accA;
    }
    __syncthreads();

    {
        int p = t >> 5, c4 = t & 31;
        size_t nn = (size_t)gbase + n0 + p;
        float4 vv = *(const float4*)&g_V[nn * CC + 4 * c4];
        float a = s_attn[p][c4 >> 3];
        float4 rr = make_float4(a * vv.x, a * vv.y, a * vv.z, a * vv.w);
        *(float4*)&out[nn * CC + 4 * c4] = rr;
    }
}

// ---------------------------------------------------------------------------
extern "C" void kernel_launch(void* const* d_in, const int* in_sizes, int n_in,
                              void* d_out, int out_size) {
    (void)in_sizes; (void)n_in; (void)out_size;
    const float* pcd   = (const float*)d_in[0];
    const float* coord = (const float*)d_in[1];
    const float* Wq    = (const float*)d_in[3];
    const float* bq    = (const float*)d_in[4];
    const float* Wk    = (const float*)d_in[5];
    const float* bk    = (const float*)d_in[6];
    const float* Wv    = (const float*)d_in[7];
    const float* bv    = (const float*)d_in[8];
    float* out = (float*)d_out;

    constexpr int SMEMB = (int)sizeof(KnnS) > (int)sizeof(GemmS)
                        ? (int)sizeof(KnnS) : (int)sizeof(GemmS);
    static_assert(SMEMB <= 60 * 1024, "smem");
    cudaFuncSetAttribute(fused_kg_kernel,
                         cudaFuncAttributeMaxDynamicSharedMemorySize, SMEMB);

    prep_kernel<<<(5 * 64 * CC + SS * CC + 255) / 256, 256>>>(Wq, Wv, Wk, bk);
    fused_kg_kernel<<<18 * 256, 256, SMEMB>>>(coord, pcd, bq, bk, bv);
    attn_kernel<<<BN / APP, 256>>>(out);
}

// round 16
// speedup vs baseline: 1.0620x; 1.0620x over previous
#include <cuda_runtime.h>

#define BB 8
#define NN 2048
#define BN (BB * NN)
#define CC 128
#define HH 4
#define DD 32
#define SS 3
#define KNB 16
#define KT 48
#define MT 32          // GEMM m-tile (fused k-paired version)
#define APP 8          // points per attn block (2 warps each)
#define NJOB 54        // 48 nbr + 3 own + 3 bk
#define CAP 256        // knn candidate capacity per warp

#define FULLMASK 0xffffffffu
typedef unsigned long long ull;

__device__ int   g_knn[BN * KT];
__device__ float g_Q[BN * CC];
__device__ float g_V[BN * CC];
__device__ float g_KF[(SS * BN + SS) * CC];   // + SS rows of bk at the tail
__device__ ull   g_Wp[5 * 64 * CC];           // k-paired weights (W[2k2][c], W[2k2+1][c])

// ---- f32x2 packed-FMA helpers (full fp32 precision, 2 FMA / instr) --------
__device__ __forceinline__ ull pk2(float lo, float hi) {
    ull r; asm("mov.b64 %0, {%1,%2};" : "=l"(r) : "f"(lo), "f"(hi)); return r;
}
__device__ __forceinline__ void fma2(ull& d, ull a, ull b) {
    asm("fma.rn.f32x2 %0, %1, %2, %0;" : "+l"(d) : "l"(a), "l"(b));
}
__device__ __forceinline__ float2 upk2(ull v) {
    float2 f; asm("mov.b64 {%0,%1}, %2;" : "=f"(f.x), "=f"(f.y) : "l"(v)); return f;
}

// ---------------------------------------------------------------------------
// Kernel 0: prep — k-paired weights + bk tail rows of g_KF.
// ---------------------------------------------------------------------------
__global__ __launch_bounds__(256) void prep_kernel(
    const float* __restrict__ Wq, const float* __restrict__ Wv,
    const float* __restrict__ Wk, const float* __restrict__ bk) {
    const int id = blockIdx.x * 256 + threadIdx.x;
    if (id < 5 * 64 * CC) {
        int y = id >> 13, r = id & 8191, k2 = r >> 7, c = r & 127;
        const float* Ws = (y == 0) ? Wq : (y == 1) ? Wv : Wk + (y - 2) * CC * CC;
        g_Wp[id] = pk2(Ws[(2 * k2) * CC + c], Ws[(2 * k2 + 1) * CC + c]);
    } else if (id - 5 * 64 * CC < SS * CC) {
        int r = id - 5 * 64 * CC;
        g_KF[(size_t)(SS * BN + r / CC) * CC + (r % CC)] = bk[r];
    }
}

// ---------------------------------------------------------------------------
// Shared-memory layouts for the fused kernel (union via dynamic smem)
// ---------------------------------------------------------------------------
struct KnnS {
    float4 c4[NN];          // (x, y, z, |p|^2)       32 KB
    ull    cand[8][CAP];    // compacted candidates   16 KB
    ull    buf[8][64];      // sort buffer             4 KB
};
struct GemmS {
    float XsT[CC][34];      // A tile transposed [k][m]   17.4 KB
    ull   As[64][34];       // A k-pairs [k2][m]          17.4 KB
};

// ---------------------------------------------------------------------------
// kNN body (exact R7/R14): top-48 per query, one warp per query.
// ---------------------------------------------------------------------------
__device__ __forceinline__ void knn_body(char* smraw, const float* __restrict__ coord,
                                         int bx) {
    KnnS* K = (KnnS*)smraw;
    const int t = threadIdx.x;
    const int lane = t & 31, w = t >> 5;
    const int b = bx >> 8;                 // 256 blocks per batch
    const int n0 = (bx & 255) * 8;
    const float* cb = coord + (size_t)b * NN * 3;

    for (int j = t; j < NN; j += 256) {
        float x = cb[3 * j], y = cb[3 * j + 1], z = cb[3 * j + 2];
        K->c4[j] = make_float4(x, y, z, fmaf(x, x, fmaf(y, y, z * z)));
    }
    __syncthreads();

    const int n = n0 + w;
    const float4 o = K->c4[n];

    unsigned kkey[64];
    unsigned m1 = 0xffffffffu, m2 = 0xffffffffu;
    #pragma unroll
    for (int s = 0; s < 64; s++) {
        int j = lane + (s << 5);
        float4 c = K->c4[j];
        float dot = fmaf(o.x, c.x, fmaf(o.y, c.y, o.z * c.z));
        float d = fmaf(-2.0f, dot, o.w + c.w);         // matches reference formula
        unsigned u = __float_as_uint(d);
        u = (u & 0x80000000u) ? ~u : (u | 0x80000000u);  // monotone total order
        kkey[s] = u;
        if (u < m1) { m2 = m1; m1 = u; } else if (u < m2) { m2 = u; }
    }

    unsigned lo = __reduce_min_sync(FULLMASK, m1);
    unsigned hi = __reduce_max_sync(FULLMASK, m2);    // >= 64 keys <= hi

    // ---- compact all keys <= hi into smem (ballot/popc; count in base) ----
    int base = 0;
    #pragma unroll
    for (int s = 0; s < 64; s++) {
        bool q = (kkey[s] <= hi);
        unsigned mm = __ballot_sync(FULLMASK, q);
        if (q) {
            int pos = base + __popc(mm & ((1u << lane) - 1u));
            if (pos < CAP)
                K->cand[w][pos] = ((ull)kkey[s] << 32) | (unsigned)(lane + (s << 5));
        }
        base += __popc(mm);
    }
    __syncwarp();

    unsigned T;
    if (base <= CAP) {
        unsigned ck[8];
        #pragma unroll
        for (int sl = 0; sl < 8; sl++) {
            int p = lane + (sl << 5);
            ck[sl] = (p < base) ? (unsigned)(K->cand[w][p] >> 32) : 0xffffffffu;
        }
        for (;;) {
            if (lo >= hi) { T = lo; break; }
            unsigned mid = lo + ((hi - lo) >> 1);
            unsigned c = 0;
            #pragma unroll
            for (int sl = 0; sl < 8; sl++) c += (ck[sl] <= mid) ? 1u : 0u;
            c = __reduce_add_sync(FULLMASK, c);
            if (c == KT) { T = mid; break; }
            if (c > KT) hi = mid; else lo = mid + 1;
        }
        K->buf[w][lane] = ~0ull;
        K->buf[w][lane + 32] = ~0ull;
        __syncwarp();
        int bs = 0;
        #pragma unroll
        for (int sl = 0; sl < 8; sl++) {
            int p = lane + (sl << 5);
            bool q = (ck[sl] <= T);
            unsigned mm = __ballot_sync(FULLMASK, q);
            if (q) {
                int pos = bs + __popc(mm & ((1u << lane) - 1u));
                if (pos < 64) K->buf[w][pos] = K->cand[w][p];
            }
            bs += __popc(mm);
        }
    } else {
        for (;;) {
            if (lo >= hi) { T = lo; break; }
            unsigned mid = lo + ((hi - lo) >> 1);
            unsigned c = 0;
            #pragma unroll
            for (int s = 0; s < 64; s++) c += (kkey[s] <= mid) ? 1u : 0u;
            c = __reduce_add_sync(FULLMASK, c);
            if (c == KT) { T = mid; break; }
            if (c > KT) hi = mid; else lo = mid + 1;
        }
        K->buf[w][lane] = ~0ull;
        K->buf[w][lane + 32] = ~0ull;
        __syncwarp();
        int bs = 0;
        #pragma unroll
        for (int s = 0; s < 64; s++) {
            bool q = (kkey[s] <= T);
            unsigned mm = __ballot_sync(FULLMASK, q);
            if (q) {
                int pos = bs + __popc(mm & ((1u << lane) - 1u));
                if (pos < 64)
                    K->buf[w][pos] = ((ull)kkey[s] << 32) | (unsigned)(lane + (s << 5));
            }
            bs += __popc(mm);
        }
    }
    __syncwarp();

    // ---- bitonic sort of 64 u64 keys, 2 per lane -> exact (dist, idx) order
    ull v0 = K->buf[w][lane];
    ull v1 = K->buf[w][lane + 32];
    #pragma unroll
    for (int k2 = 2; k2 <= 64; k2 <<= 1) {
        #pragma unroll
        for (int j2 = k2 >> 1; j2 > 0; j2 >>= 1) {
            if (j2 == 32) {
                ull a = v0 < v1 ? v0 : v1;
                ull bm = v0 < v1 ? v1 : v0;
                v0 = a; v1 = bm;
            } else {
                bool low = ((lane & j2) == 0);
                bool up0 = ((lane & k2) == 0);
                bool up1 = (((lane + 32) & k2) == 0);
                ull o0 = __shfl_xor_sync(FULLMASK, v0, j2);
                ull o1 = __shfl_xor_sync(FULLMASK, v1, j2);
                bool t0 = (low == up0);
                bool t1 = (low == up1);
                v0 = t0 ? (v0 < o0 ? v0 : o0) : (v0 > o0 ? v0 : o0);
                v1 = t1 ? (v1 < o1 ? v1 : o1) : (v1 > o1 ? v1 : o1);
            }
        }
    }

    int* outp = g_knn + ((size_t)b * NN + n) * KT;
    outp[lane] = (int)(v0 & 0xffffffffu);
    if (lane < KT - 32) outp[32 + lane] = (int)(v1 & 0xffffffffu);
}

// ---------------------------------------------------------------------------
// GEMM body: k-paired f32x2, MT=32 rows x 128 cols, 256 threads (unchanged).
// ---------------------------------------------------------------------------
__device__ __forceinline__ void gemm_body(char* smraw,
                                          const float* __restrict__ A,
                                          const ull* __restrict__ wbase,
                                          const float* __restrict__ bias,
                                          float* __restrict__ O, int m0) {
    GemmS* G = (GemmS*)smraw;
    const int t = threadIdx.x;
    const int tx = t & 31, ty = t >> 5;    // ty 0..7 -> rows ty*4..ty*4+3

    #pragma unroll
    for (int s = t; s < MT * 32; s += 256) {
        int m = s >> 5, j = s & 31;
        float4 v = *(const float4*)&A[(size_t)(m0 + m) * CC + 4 * j];
        G->XsT[4 * j + 0][m] = v.x;
        G->XsT[4 * j + 1][m] = v.y;
        G->XsT[4 * j + 2][m] = v.z;
        G->XsT[4 * j + 3][m] = v.w;
    }
    __syncthreads();

    #pragma unroll
    for (int i = t; i < 64 * MT; i += 256) {
        int k2 = i >> 5, m = i & 31;
        *(float2*)&G->As[k2][m] = make_float2(G->XsT[2 * k2][m], G->XsT[2 * k2 + 1][m]);
    }
    __syncthreads();

    ull acc[4][4];
    #pragma unroll
    for (int mi = 0; mi < 4; mi++)
        #pragma unroll
        for (int ci = 0; ci < 4; ci++) acc[mi][ci] = 0;

    #pragma unroll 8
    for (int k2 = 0; k2 < 64; k2++) {
        const ulonglong2* wrow = (const ulonglong2*)(wbase + k2 * CC);
        ulonglong2 q0 = __ldg(wrow + tx);        // cols 2tx, 2tx+1
        ulonglong2 q1 = __ldg(wrow + 32 + tx);   // cols 64+2tx, 64+2tx+1
        ulonglong2 a01 = *(const ulonglong2*)&G->As[k2][ty * 4];
        ulonglong2 a23 = *(const ulonglong2*)&G->As[k2][ty * 4 + 2];
        fma2(acc[0][0], a01.x, q0.x); fma2(acc[0][1], a01.x, q0.y);
        fma2(acc[0][2], a01.x, q1.x); fma2(acc[0][3], a01.x, q1.y);
        fma2(acc[1][0], a01.y, q0.x); fma2(acc[1][1], a01.y, q0.y);
        fma2(acc[1][2], a01.y, q1.x); fma2(acc[1][3], a01.y, q1.y);
        fma2(acc[2][0], a23.x, q0.x); fma2(acc[2][1], a23.x, q0.y);
        fma2(acc[2][2], a23.x, q1.x); fma2(acc[2][3], a23.x, q1.y);
        fma2(acc[3][0], a23.y, q0.x); fma2(acc[3][1], a23.y, q0.y);
        fma2(acc[3][2], a23.y, q1.x); fma2(acc[3][3], a23.y, q1.y);
    }

    float2 b0 = *(const float2*)&bias[2 * tx];
    float2 b1 = *(const float2*)&bias[64 + 2 * tx];
    #pragma unroll
    for (int mi = 0; mi < 4; mi++) {
        int m = m0 + ty * 4 + mi;
        float2 f00 = upk2(acc[mi][0]), f01 = upk2(acc[mi][1]);
        float2 f10 = upk2(acc[mi][2]), f11 = upk2(acc[mi][3]);
        float2 r0 = make_float2(f00.x + f00.y + b0.x, f01.x + f01.y + b0.y);
        float2 r1 = make_float2(f10.x + f10.y + b1.x, f11.x + f11.y + b1.y);
        *(float2*)&O[(size_t)m * CC + 2 * tx] = r0;
        *(float2*)&O[(size_t)m * CC + 64 + 2 * tx] = r1;
    }
}

// ---------------------------------------------------------------------------
// Fused kNN + GEMM kernel: 256 groups x (8 knn + 10 gemm) blocks.
// ---------------------------------------------------------------------------
__global__ __launch_bounds__(256, 3) void fused_kg_kernel(
    const float* __restrict__ coord, const float* __restrict__ pcd,
    const float* __restrict__ bq, const float* __restrict__ bk,
    const float* __restrict__ bv) {
    extern __shared__ char smraw[];
    const int grp = blockIdx.x / 18;      // 0..255
    const int r   = blockIdx.x % 18;
    if (r < 8) {
        knn_body(smraw, coord, grp * 8 + r);           // 2048 knn blocks
    } else {
        int gid = grp * 10 + (r - 8);                  // 0..2559
        int y = gid >> 9, mblk = gid & 511;            // 5 x 512 m-tiles
        const ull* wbase = g_Wp + (size_t)y * 64 * CC;
        const float* bias;
        float* O;
        if (y == 0)      { bias = bq; O = g_Q; }
        else if (y == 1) { bias = bv; O = g_V; }
        else             { bias = bk + (y - 2) * CC; O = g_KF + (size_t)(y - 2) * BN * CC; }
        gemm_body(smraw, pcd, wbase, bias, O, mblk * MT);
    }
}

// ---------------------------------------------------------------------------
// Kernel 2: attention via Kf gathers — 2 warps per point (27 jobs each),
// software-pipelined 7-chunk loop. Halves per-warp latency chain vs R14.
// ---------------------------------------------------------------------------
__global__ __launch_bounds__(512, 2) void attn_kernel(float* __restrict__ out)
{
    __shared__ int   s_kn[APP][KT];
    __shared__ float s_raw[APP][HH][56];
    __shared__ float s_attn[APP][HH];

    const int t = threadIdx.x;
    const int lane = t & 31, w = t >> 5;       // w 0..15
    const int p = w >> 1, sub = w & 1;         // point, half-job-set
    const int g = lane & 7, kq = lane >> 3;
    const int b = blockIdx.x / (NN / APP);
    const int n0 = (blockIdx.x % (NN / APP)) * APP;
    const int gbase = b * NN;

    for (int idx = t; idx < APP * KT; idx += 512) {
        int pp = idx / KT, j = idx % KT;
        s_kn[pp][j] = g_knn[(size_t)(gbase + n0 + pp) * KT + j];
    }
    __syncthreads();

    const int n = n0 + p;

    ulonglong2 qm[4];
    {
        const float* qrow = g_Q + (size_t)(gbase + n) * CC;
        #pragma unroll
        for (int m = 0; m < 4; m++)
            qm[m] = *(const ulonglong2*)&qrow[4 * g + 32 * m];
    }

    const int jbase = 27 * sub;                // jobs [jbase, jbase+27)
    auto job_ext = [&](int jid) -> int {       // safe for jid in [0, 63]
        int i = (jid >= 36) ? 2 : (jid >= 18 ? 1 : 0);
        int r = jid - 18 * i;
        if (r < 16)  return i * BN + gbase + s_kn[p][i * KNB + r];
        if (r == 16) return i * BN + gbase + n;
        return SS * BN + (i < SS ? i : SS - 1);
    };
    int je = job_ext(jbase + lane);            // lane 27..31: harmless extras

    // ---- prologue: load chunk 0 ----
    ulonglong2 c0, c1, c2, c3;
    {
        int jext = __shfl_sync(FULLMASK, je, kq);
        const float* kf = g_KF + (size_t)jext * CC;
        c0 = *(const ulonglong2*)&kf[4 * g];
        c1 = *(const ulonglong2*)&kf[4 * g + 32];
        c2 = *(const ulonglong2*)&kf[4 * g + 64];
        c3 = *(const ulonglong2*)&kf[4 * g + 96];
    }

    #pragma unroll
    for (int ch = 0; ch < 7; ch++) {
        // ---- prefetch chunk ch+1 ----
        ulonglong2 p0, p1, p2, p3;
        if (ch < 6) {
            int jn = __shfl_sync(FULLMASK, je, 4 * (ch + 1) + kq);
            const float* kfn = g_KF + (size_t)jn * CC;
            p0 = *(const ulonglong2*)&kfn[4 * g];
            p1 = *(const ulonglong2*)&kfn[4 * g + 32];
            p2 = *(const ulonglong2*)&kfn[4 * g + 64];
            p3 = *(const ulonglong2*)&kfn[4 * g + 96];
        }

        // ---- reduce current chunk ----
        ull a0 = 0, a1 = 0, a2 = 0, a3 = 0;
        fma2(a0, c0.x, qm[0].x); fma2(a0, c0.y, qm[0].y);
        fma2(a1, c1.x, qm[1].x); fma2(a1, c1.y, qm[1].y);
        fma2(a2, c2.x, qm[2].x); fma2(a2, c2.y, qm[2].y);
        fma2(a3, c3.x, qm[3].x); fma2(a3, c3.y, qm[3].y);
        float2 f0 = upk2(a0), f1 = upk2(a1), f2 = upk2(a2), f3 = upk2(a3);
        float s0 = f0.x + f0.y, s1 = f1.x + f1.y;
        float s2 = f2.x + f2.y, s3 = f3.x + f3.y;
        #pragma unroll
        for (int off = 1; off <= 4; off <<= 1) {
            s0 += __shfl_xor_sync(FULLMASK, s0, off);
            s1 += __shfl_xor_sync(FULLMASK, s1, off);
            s2 += __shfl_xor_sync(FULLMASK, s2, off);
            s3 += __shfl_xor_sync(FULLMASK, s3, off);
        }
        int jr = 4 * ch + kq;                  // job index within this half
        float val = (g == 0) ? s0 : (g == 1) ? s1 : (g == 2) ? s2 : s3;
        if (g < 4 && jr < 27) s_raw[p][g][jbase + jr] = val;

        if (ch < 6) { c0 = p0; c1 = p1; c2 = p2; c3 = p3; }
    }
    __syncthreads();

    if (t < APP * HH) {
        const int pp = t >> 2, h = t & 3;
        const float inv = 0.17677669529663687f;   // 1/sqrt(32)
        float accA = 0.0f;
        #pragma unroll
        for (int i = 0; i < SS; i++) {
            const float* raw = &s_raw[pp][h][i * 18];
            float corr = raw[17] - raw[16];        // q.bk - q.Kf'[n]
            float l[KNB];
            float mx = -1e30f;
            #pragma unroll
            for (int k = 0; k < KNB; k++) {
                l[k] = inv * (raw[k] + corr);
                mx = fmaxf(mx, l[k]);
            }
            float se = 0.0f, sl = 0.0f;
            #pragma unroll
            for (int k = 0; k < KNB; k++) {
                float e = __expf(l[k] - mx);
                se += e;
                sl = fmaf(e, l[k], sl);
            }
            accA += sl / se;
        }
        s_attn[pp][h] = accA;
    }
    __syncthreads();

    if (t < APP * 32) {
        int pp = t >> 5, c4 = t & 31;
        size_t nn = (size_t)gbase + n0 + pp;
        float4 vv = *(const float4*)&g_V[nn * CC + 4 * c4];
        float a = s_attn[pp][c4 >> 3];
        float4 rr = make_float4(a * vv.x, a * vv.y, a * vv.z, a * vv.w);
        *(float4*)&out[nn * CC + 4 * c4] = rr;
    }
}

// ---------------------------------------------------------------------------
extern "C" void kernel_launch(void* const* d_in, const int* in_sizes, int n_in,
                              void* d_out, int out_size) {
    (void)in_sizes; (void)n_in; (void)out_size;
    const float* pcd   = (const float*)d_in[0];
    const float* coord = (const float*)d_in[1];
    const float* Wq    = (const float*)d_in[3];
    const float* bq    = (const float*)d_in[4];
    const float* Wk    = (const float*)d_in[5];
    const float* bk    = (const float*)d_in[6];
    const float* Wv    = (const float*)d_in[7];
    const float* bv    = (const float*)d_in[8];
    float* out = (float*)d_out;

    constexpr int SMEMB = (int)sizeof(KnnS) > (int)sizeof(GemmS)
                        ? (int)sizeof(KnnS) : (int)sizeof(GemmS);
    static_assert(SMEMB <= 60 * 1024, "smem");
    cudaFuncSetAttribute(fused_kg_kernel,
                         cudaFuncAttributeMaxDynamicSharedMemorySize, SMEMB);

    prep_kernel<<<(5 * 64 * CC + SS * CC + 255) / 256, 256>>>(Wq, Wv, Wk, bk);
    fused_kg_kernel<<<18 * 256, 256, SMEMB>>>(coord, pcd, bq, bk, bv);
    attn_kernel<<<BN / APP, 512>>>(out);
}

// round 17
// speedup vs baseline: 1.0944x; 1.0305x over previous
#include <cuda_runtime.h>

#define BB 8
#define NN 2048
#define BN (BB * NN)
#define CC 128
#define HH 4
#define DD 32
#define SS 3
#define KNB 16
#define KT 48
#define MT 32          // GEMM m-tile (fused k-paired version)
#define APP 8          // points per attn block (1 warp each)
#define NJOB 54        // 48 nbr + 3 own + 3 bk
#define CAP 256        // knn candidate capacity per warp

#define FULLMASK 0xffffffffu
typedef unsigned long long ull;

__device__ int   g_knn[BN * KT];
__device__ float g_Q[BN * CC];
__device__ float g_V[BN * CC];
__device__ float g_KF[(SS * BN + SS) * CC];   // + SS rows of bk at the tail
__device__ ull   g_Wp[5 * 64 * CC];           // k-paired weights (W[2k2][c], W[2k2+1][c])

// ---- f32x2 packed-FMA helpers (full fp32 precision, 2 FMA / instr) --------
__device__ __forceinline__ ull pk2(float lo, float hi) {
    ull r; asm("mov.b64 %0, {%1,%2};" : "=l"(r) : "f"(lo), "f"(hi)); return r;
}
__device__ __forceinline__ void fma2(ull& d, ull a, ull b) {
    asm("fma.rn.f32x2 %0, %1, %2, %0;" : "+l"(d) : "l"(a), "l"(b));
}
__device__ __forceinline__ float2 upk2(ull v) {
    float2 f; asm("mov.b64 {%0,%1}, %2;" : "=f"(f.x), "=f"(f.y) : "l"(v)); return f;
}

// ---------------------------------------------------------------------------
// Kernel 0: prep — k-paired weights + bk tail rows of g_KF.
// ---------------------------------------------------------------------------
__global__ __launch_bounds__(256) void prep_kernel(
    const float* __restrict__ Wq, const float* __restrict__ Wv,
    const float* __restrict__ Wk, const float* __restrict__ bk) {
    const int id = blockIdx.x * 256 + threadIdx.x;
    if (id < 5 * 64 * CC) {
        int y = id >> 13, r = id & 8191, k2 = r >> 7, c = r & 127;
        const float* Ws = (y == 0) ? Wq : (y == 1) ? Wv : Wk + (y - 2) * CC * CC;
        g_Wp[id] = pk2(Ws[(2 * k2) * CC + c], Ws[(2 * k2 + 1) * CC + c]);
    } else if (id - 5 * 64 * CC < SS * CC) {
        int r = id - 5 * 64 * CC;
        g_KF[(size_t)(SS * BN + r / CC) * CC + (r % CC)] = bk[r];
    }
}

// ---------------------------------------------------------------------------
// Shared-memory layouts for the fused kernel (union via dynamic smem)
// ---------------------------------------------------------------------------
struct KnnS {
    float4 c4[NN];          // (x, y, z, |p|^2)       32 KB
    ull    cand[8][CAP];    // compacted candidates   16 KB
    ull    buf[8][64];      // sort buffer             4 KB
};
struct GemmS {
    ull As[64][34];         // A k-pairs [k2][m] = row data viewed as pairs  17.4 KB
};

// ---------------------------------------------------------------------------
// kNN body (exact R7/R14): top-48 per query, one warp per query.
// ---------------------------------------------------------------------------
__device__ __forceinline__ void knn_body(char* smraw, const float* __restrict__ coord,
                                         int bx) {
    KnnS* K = (KnnS*)smraw;
    const int t = threadIdx.x;
    const int lane = t & 31, w = t >> 5;
    const int b = bx >> 8;                 // 256 blocks per batch
    const int n0 = (bx & 255) * 8;
    const float* cb = coord + (size_t)b * NN * 3;

    for (int j = t; j < NN; j += 256) {
        float x = cb[3 * j], y = cb[3 * j + 1], z = cb[3 * j + 2];
        K->c4[j] = make_float4(x, y, z, fmaf(x, x, fmaf(y, y, z * z)));
    }
    __syncthreads();

    const int n = n0 + w;
    const float4 o = K->c4[n];

    unsigned kkey[64];
    unsigned m1 = 0xffffffffu, m2 = 0xffffffffu;
    #pragma unroll
    for (int s = 0; s < 64; s++) {
        int j = lane + (s << 5);
        float4 c = K->c4[j];
        float dot = fmaf(o.x, c.x, fmaf(o.y, c.y, o.z * c.z));
        float d = fmaf(-2.0f, dot, o.w + c.w);         // matches reference formula
        unsigned u = __float_as_uint(d);
        u = (u & 0x80000000u) ? ~u : (u | 0x80000000u);  // monotone total order
        kkey[s] = u;
        if (u < m1) { m2 = m1; m1 = u; } else if (u < m2) { m2 = u; }
    }

    unsigned lo = __reduce_min_sync(FULLMASK, m1);
    unsigned hi = __reduce_max_sync(FULLMASK, m2);    // >= 64 keys <= hi

    // ---- compact all keys <= hi into smem (ballot/popc; count in base) ----
    int base = 0;
    #pragma unroll
    for (int s = 0; s < 64; s++) {
        bool q = (kkey[s] <= hi);
        unsigned mm = __ballot_sync(FULLMASK, q);
        if (q) {
            int pos = base + __popc(mm & ((1u << lane) - 1u));
            if (pos < CAP)
                K->cand[w][pos] = ((ull)kkey[s] << 32) | (unsigned)(lane + (s << 5));
        }
        base += __popc(mm);
    }
    __syncwarp();

    unsigned T;
    if (base <= CAP) {
        unsigned ck[8];
        #pragma unroll
        for (int sl = 0; sl < 8; sl++) {
            int p = lane + (sl << 5);
            ck[sl] = (p < base) ? (unsigned)(K->cand[w][p] >> 32) : 0xffffffffu;
        }
        for (;;) {
            if (lo >= hi) { T = lo; break; }
            unsigned mid = lo + ((hi - lo) >> 1);
            unsigned c = 0;
            #pragma unroll
            for (int sl = 0; sl < 8; sl++) c += (ck[sl] <= mid) ? 1u : 0u;
            c = __reduce_add_sync(FULLMASK, c);
            if (c == KT) { T = mid; break; }
            if (c > KT) hi = mid; else lo = mid + 1;
        }
        K->buf[w][lane] = ~0ull;
        K->buf[w][lane + 32] = ~0ull;
        __syncwarp();
        int bs = 0;
        #pragma unroll
        for (int sl = 0; sl < 8; sl++) {
            int p = lane + (sl << 5);
            bool q = (ck[sl] <= T);
            unsigned mm = __ballot_sync(FULLMASK, q);
            if (q) {
                int pos = bs + __popc(mm & ((1u << lane) - 1u));
                if (pos < 64) K->buf[w][pos] = K->cand[w][p];
            }
            bs += __popc(mm);
        }
    } else {
        for (;;) {
            if (lo >= hi) { T = lo; break; }
            unsigned mid = lo + ((hi - lo) >> 1);
            unsigned c = 0;
            #pragma unroll
            for (int s = 0; s < 64; s++) c += (kkey[s] <= mid) ? 1u : 0u;
            c = __reduce_add_sync(FULLMASK, c);
            if (c == KT) { T = mid; break; }
            if (c > KT) hi = mid; else lo = mid + 1;
        }
        K->buf[w][lane] = ~0ull;
        K->buf[w][lane + 32] = ~0ull;
        __syncwarp();
        int bs = 0;
        #pragma unroll
        for (int s = 0; s < 64; s++) {
            bool q = (kkey[s] <= T);
            unsigned mm = __ballot_sync(FULLMASK, q);
            if (q) {
                int pos = bs + __popc(mm & ((1u << lane) - 1u));
                if (pos < 64)
                    K->buf[w][pos] = ((ull)kkey[s] << 32) | (unsigned)(lane + (s << 5));
            }
            bs += __popc(mm);
        }
    }
    __syncwarp();

    // ---- bitonic sort of 64 u64 keys, 2 per lane -> exact (dist, idx) order
    ull v0 = K->buf[w][lane];
    ull v1 = K->buf[w][lane + 32];
    #pragma unroll
    for (int k2 = 2; k2 <= 64; k2 <<= 1) {
        #pragma unroll
        for (int j2 = k2 >> 1; j2 > 0; j2 >>= 1) {
            if (j2 == 32) {
                ull a = v0 < v1 ? v0 : v1;
                ull bm = v0 < v1 ? v1 : v0;
                v0 = a; v1 = bm;
            } else {
                bool low = ((lane & j2) == 0);
                bool up0 = ((lane & k2) == 0);
                bool up1 = (((lane + 32) & k2) == 0);
                ull o0 = __shfl_xor_sync(FULLMASK, v0, j2);
                ull o1 = __shfl_xor_sync(FULLMASK, v1, j2);
                bool t0 = (low == up0);
                bool t1 = (low == up1);
                v0 = t0 ? (v0 < o0 ? v0 : o0) : (v0 > o0 ? v0 : o0);
                v1 = t1 ? (v1 < o1 ? v1 : o1) : (v1 > o1 ? v1 : o1);
            }
        }
    }

    int* outp = g_knn + ((size_t)b * NN + n) * KT;
    outp[lane] = (int)(v0 & 0xffffffffu);
    if (lane < KT - 32) outp[32 + lane] = (int)(v1 & 0xffffffffu);
}

// ---------------------------------------------------------------------------
// GEMM body: k-paired f32x2, MT=32 rows x 128 cols, 256 threads.
// Direct pair load: As[k2][m] = ((ull*)&A[m*CC])[k2]  (no staging transpose).
// ---------------------------------------------------------------------------
__device__ __forceinline__ void gemm_body(char* smraw,
                                          const float* __restrict__ A,
                                          const ull* __restrict__ wbase,
                                          const float* __restrict__ bias,
                                          float* __restrict__ O, int m0) {
    GemmS* G = (GemmS*)smraw;
    const int t = threadIdx.x;
    const int tx = t & 31, ty = t >> 5;    // ty 0..7 -> rows ty*4..ty*4+3

    // ---- load A tile as k-pairs directly (coalesced LDG.128, 2 pairs/thread)
    #pragma unroll
    for (int s = t; s < MT * 32; s += 256) {
        int m = s >> 5, k4 = s & 31;        // k4 = pair-pair index (2 pairs)
        ulonglong2 v = *(const ulonglong2*)&A[(size_t)(m0 + m) * CC + 4 * k4];
        G->As[2 * k4][m] = v.x;             // pair (A[m][4k4],   A[m][4k4+1])
        G->As[2 * k4 + 1][m] = v.y;         // pair (A[m][4k4+2], A[m][4k4+3])
    }
    __syncthreads();

    ull acc[4][4];
    #pragma unroll
    for (int mi = 0; mi < 4; mi++)
        #pragma unroll
        for (int ci = 0; ci < 4; ci++) acc[mi][ci] = 0;

    #pragma unroll 8
    for (int k2 = 0; k2 < 64; k2++) {
        const ulonglong2* wrow = (const ulonglong2*)(wbase + k2 * CC);
        ulonglong2 q0 = __ldg(wrow + tx);        // cols 2tx, 2tx+1
        ulonglong2 q1 = __ldg(wrow + 32 + tx);   // cols 64+2tx, 64+2tx+1
        ulonglong2 a01 = *(const ulonglong2*)&G->As[k2][ty * 4];
        ulonglong2 a23 = *(const ulonglong2*)&G->As[k2][ty * 4 + 2];
        fma2(acc[0][0], a01.x, q0.x); fma2(acc[0][1], a01.x, q0.y);
        fma2(acc[0][2], a01.x, q1.x); fma2(acc[0][3], a01.x, q1.y);
        fma2(acc[1][0], a01.y, q0.x); fma2(acc[1][1], a01.y, q0.y);
        fma2(acc[1][2], a01.y, q1.x); fma2(acc[1][3], a01.y, q1.y);
        fma2(acc[2][0], a23.x, q0.x); fma2(acc[2][1], a23.x, q0.y);
        fma2(acc[2][2], a23.x, q1.x); fma2(acc[2][3], a23.x, q1.y);
        fma2(acc[3][0], a23.y, q0.x); fma2(acc[3][1], a23.y, q0.y);
        fma2(acc[3][2], a23.y, q1.x); fma2(acc[3][3], a23.y, q1.y);
    }

    float2 b0 = *(const float2*)&bias[2 * tx];
    float2 b1 = *(const float2*)&bias[64 + 2 * tx];
    #pragma unroll
    for (int mi = 0; mi < 4; mi++) {
        int m = m0 + ty * 4 + mi;
        float2 f00 = upk2(acc[mi][0]), f01 = upk2(acc[mi][1]);
        float2 f10 = upk2(acc[mi][2]), f11 = upk2(acc[mi][3]);
        float2 r0 = make_float2(f00.x + f00.y + b0.x, f01.x + f01.y + b0.y);
        float2 r1 = make_float2(f10.x + f10.y + b1.x, f11.x + f11.y + b1.y);
        *(float2*)&O[(size_t)m * CC + 2 * tx] = r0;
        *(float2*)&O[(size_t)m * CC + 64 + 2 * tx] = r1;
    }
}

// ---------------------------------------------------------------------------
// Fused kNN + GEMM kernel: 256 groups x (8 knn + 10 gemm) blocks.
// ---------------------------------------------------------------------------
__global__ __launch_bounds__(256, 3) void fused_kg_kernel(
    const float* __restrict__ coord, const float* __restrict__ pcd,
    const float* __restrict__ bq, const float* __restrict__ bk,
    const float* __restrict__ bv) {
    extern __shared__ char smraw[];
    const int grp = blockIdx.x / 18;      // 0..255
    const int r   = blockIdx.x % 18;
    if (r < 8) {
        knn_body(smraw, coord, grp * 8 + r);           // 2048 knn blocks
    } else {
        int gid = grp * 10 + (r - 8);                  // 0..2559
        int y = gid >> 9, mblk = gid & 511;            // 5 x 512 m-tiles
        const ull* wbase = g_Wp + (size_t)y * 64 * CC;
        const float* bias;
        float* O;
        if (y == 0)      { bias = bq; O = g_Q; }
        else if (y == 1) { bias = bv; O = g_V; }
        else             { bias = bk + (y - 2) * CC; O = g_KF + (size_t)(y - 2) * BN * CC; }
        gemm_body(smraw, pcd, wbase, bias, O, mblk * MT);
    }
}

// ---------------------------------------------------------------------------
// Kernel 2: attention via Kf gathers — software-pipelined chunk loop (R14).
// ---------------------------------------------------------------------------
__global__ __launch_bounds__(256, 4) void attn_kernel(float* __restrict__ out)
{
    __shared__ int   s_kn[APP][KT];
    __shared__ float s_raw[APP][HH][56];
    __shared__ float s_attn[APP][HH];

    const int t = threadIdx.x;
    const int lane = t & 31, w = t >> 5;
    const int g = lane & 7, kq = lane >> 3;
    const int b = blockIdx.x / (NN / APP);
    const int n0 = (blockIdx.x % (NN / APP)) * APP;
    const int gbase = b * NN;

    for (int idx = t; idx < APP * KT; idx += 256) {
        int p = idx / KT, j = idx % KT;
        s_kn[p][j] = g_knn[(size_t)(gbase + n0 + p) * KT + j];
    }
    __syncthreads();

    const int n = n0 + w;

    ulonglong2 qm[4];
    {
        const float* qrow = g_Q + (size_t)(gbase + n) * CC;
        #pragma unroll
        for (int m = 0; m < 4; m++)
            qm[m] = *(const ulonglong2*)&qrow[4 * g + 32 * m];
    }

    auto job_ext = [&](int jid) -> int {
        int i = (jid >= 36) ? 2 : (jid >= 18 ? 1 : 0);
        int r = jid - 18 * i;
        if (r < 16)  return i * BN + gbase + s_kn[w][i * KNB + r];
        if (r == 16) return i * BN + gbase + n;
        return SS * BN + i;
    };
    int je0 = job_ext(lane);
    int je1 = (lane < NJOB - 32) ? job_ext(32 + lane) : je0;

    // ---- prologue: load chunk 0 ----
    ulonglong2 c0, c1, c2, c3;
    {
        int jext = __shfl_sync(FULLMASK, je0, kq);
        const float* kf = g_KF + (size_t)jext * CC;
        c0 = *(const ulonglong2*)&kf[4 * g];
        c1 = *(const ulonglong2*)&kf[4 * g + 32];
        c2 = *(const ulonglong2*)&kf[4 * g + 64];
        c3 = *(const ulonglong2*)&kf[4 * g + 96];
    }

    #pragma unroll
    for (int ch = 0; ch < 14; ch++) {
        // ---- prefetch chunk ch+1 ----
        ulonglong2 p0, p1, p2, p3;
        if (ch < 13) {
            int chn = ch + 1;
            int src = (chn < 8) ? (4 * chn + kq) : (4 * (chn - 8) + kq);
            int jn = __shfl_sync(FULLMASK, (chn < 8) ? je0 : je1, src);
            const float* kfn = g_KF + (size_t)jn * CC;
            p0 = *(const ulonglong2*)&kfn[4 * g];
            p1 = *(const ulonglong2*)&kfn[4 * g + 32];
            p2 = *(const ulonglong2*)&kfn[4 * g + 64];
            p3 = *(const ulonglong2*)&kfn[4 * g + 96];
        }

        // ---- reduce current chunk ----
        ull a0 = 0, a1 = 0, a2 = 0, a3 = 0;
        fma2(a0, c0.x, qm[0].x); fma2(a0, c0.y, qm[0].y);
        fma2(a1, c1.x, qm[1].x); fma2(a1, c1.y, qm[1].y);
        fma2(a2, c2.x, qm[2].x); fma2(a2, c2.y, qm[2].y);
        fma2(a3, c3.x, qm[3].x); fma2(a3, c3.y, qm[3].y);
        float2 f0 = upk2(a0), f1 = upk2(a1), f2 = upk2(a2), f3 = upk2(a3);
        float s0 = f0.x + f0.y, s1 = f1.x + f1.y;
        float s2 = f2.x + f2.y, s3 = f3.x + f3.y;
        #pragma unroll
        for (int off = 1; off <= 4; off <<= 1) {
            s0 += __shfl_xor_sync(FULLMASK, s0, off);
            s1 += __shfl_xor_sync(FULLMASK, s1, off);
            s2 += __shfl_xor_sync(FULLMASK, s2, off);
            s3 += __shfl_xor_sync(FULLMASK, s3, off);
        }
        int jid = (ch < 8) ? (4 * ch + kq) : (32 + 4 * (ch - 8) + kq);
        float val = (g == 0) ? s0 : (g == 1) ? s1 : (g == 2) ? s2 : s3;
        if (g < 4 && jid < NJOB) s_raw[w][g][jid] = val;

        if (ch < 13) { c0 = p0; c1 = p1; c2 = p2; c3 = p3; }
    }
    __syncthreads();

    if (t < APP * HH) {
        const int p = t >> 2, h = t & 3;
        const float inv = 0.17677669529663687f;   // 1/sqrt(32)
        float accA = 0.0f;
        #pragma unroll
        for (int i = 0; i < SS; i++) {
            const float* raw = &s_raw[p][h][i * 18];
            float corr = raw[17] - raw[16];        // q.bk - q.Kf'[n]
            float l[KNB];
            float mx = -1e30f;
            #pragma unroll
            for (int k = 0; k < KNB; k++) {
                l[k] = inv * (raw[k] + corr);
                mx = fmaxf(mx, l[k]);
            }
            float se = 0.0f, sl = 0.0f;
            #pragma unroll
            for (int k = 0; k < KNB; k++) {
                float e = __expf(l[k] - mx);
                se += e;
                sl = fmaf(e, l[k], sl);
            }
            accA += sl / se;
        }
        s_attn[p][h] = accA;
    }
    __syncthreads();

    {
        int p = t >> 5, c4 = t & 31;
        size_t nn = (size_t)gbase + n0 + p;
        float4 vv = *(const float4*)&g_V[nn * CC + 4 * c4];
        float a = s_attn[p][c4 >> 3];
        float4 rr = make_float4(a * vv.x, a * vv.y, a * vv.z, a * vv.w);
        *(float4*)&out[nn * CC + 4 * c4] = rr;
    }
}

// ---------------------------------------------------------------------------
extern "C" void kernel_launch(void* const* d_in, const int* in_sizes, int n_in,
                              void* d_out, int out_size) {
    (void)in_sizes; (void)n_in; (void)out_size;
    const float* pcd   = (const float*)d_in[0];
    const float* coord = (const float*)d_in[1];
    const float* Wq    = (const float*)d_in[3];
    const float* bq    = (const float*)d_in[4];
    const float* Wk    = (const float*)d_in[5];
    const float* bk    = (const float*)d_in[6];
    const float* Wv    = (const float*)d_in[7];
    const float* bv    = (const float*)d_in[8];
    float* out = (float*)d_out;

    constexpr int SMEMB = (int)sizeof(KnnS) > (int)sizeof(GemmS)
                        ? (int)sizeof(KnnS) : (int)sizeof(GemmS);
    static_assert(SMEMB <= 60 * 1024, "smem");
    cudaFuncSetAttribute(fused_kg_kernel,
                         cudaFuncAttributeMaxDynamicSharedMemorySize, SMEMB);

    prep_kernel<<<(5 * 64 * CC + SS * CC + 255) / 256, 256>>>(Wq, Wv, Wk, bk);
    fused_kg_kernel<<<18 * 256, 256, SMEMB>>>(coord, pcd, bq, bk, bv);
    attn_kernel<<<BN / APP, 256>>>(out);
}